// round 11
// baseline (speedup 1.0000x reference)
#include <cuda_runtime.h>
#include <cuda_fp16.h>
#include <stdint.h>
#include <math.h>

// Problem constants
#define B_    2
#define S_    1024
#define H_    4096
#define NH_   32
#define HD_   128
#define M_    2048
#define NQKV_ 12288

// ---------------- device scratch (no runtime allocation) ----------------
__device__ __half g_QKVh[(size_t)M_ * NQKV_];
__device__ __half g_QKVl[(size_t)M_ * NQKV_];
__device__ __half g_Ah[(size_t)M_ * H_];
__device__ __half g_Bqh[(size_t)NQKV_ * H_];
__device__ __half g_Bql[(size_t)NQKV_ * H_];
__device__ __half g_Bdh[(size_t)H_ * H_];
__device__ __half g_Bdl[(size_t)H_ * H_];
__device__ __half g_Ch[(size_t)M_ * H_];

// ---------------- PTX helpers (portable, non-'a' features only) ----------------
__device__ __forceinline__ uint32_t smem_u32(const void* p) {
    uint32_t a;
    asm("{ .reg .u64 t; cvta.to.shared.u64 t, %1; cvt.u32.u64 %0, t; }" : "=r"(a) : "l"(p));
    return a;
}
__device__ __forceinline__ void cp_async16(uint32_t dst_smem, const void* src) {
    asm volatile("cp.async.cg.shared.global [%0], [%1], 16;"
                 :: "r"(dst_smem), "l"(src) : "memory");
}
__device__ __forceinline__ void cp_commit() {
    asm volatile("cp.async.commit_group;" ::: "memory");
}
__device__ __forceinline__ void cp_wait1() {
    asm volatile("cp.async.wait_group 1;" ::: "memory");
}
__device__ __forceinline__ void ldsm4(uint32_t* r, uint32_t addr) {
    asm volatile("ldmatrix.sync.aligned.m8n8.x4.shared.b16 {%0,%1,%2,%3}, [%4];"
                 : "=r"(r[0]), "=r"(r[1]), "=r"(r[2]), "=r"(r[3]) : "r"(addr));
}
__device__ __forceinline__ void ldsm4t(uint32_t* r, uint32_t addr) {
    asm volatile("ldmatrix.sync.aligned.m8n8.x4.trans.shared.b16 {%0,%1,%2,%3}, [%4];"
                 : "=r"(r[0]), "=r"(r[1]), "=r"(r[2]), "=r"(r[3]) : "r"(addr));
}
__device__ __forceinline__ void mma_f16(float* d, const uint32_t* a, const uint32_t* b) {
    asm volatile(
        "mma.sync.aligned.m16n8k16.row.col.f32.f16.f16.f32 "
        "{%0,%1,%2,%3}, {%4,%5,%6,%7}, {%8,%9}, {%0,%1,%2,%3};"
        : "+f"(d[0]), "+f"(d[1]), "+f"(d[2]), "+f"(d[3])
        : "r"(a[0]), "r"(a[1]), "r"(a[2]), "r"(a[3]), "r"(b[0]), "r"(b[1]));
}
__device__ __forceinline__ uint32_t pack_f16(float lo, float hi) {
    uint32_t r;
    asm("cvt.rn.f16x2.f32 %0, %1, %2;" : "=r"(r) : "f"(hi), "f"(lo));
    return r;
}
__device__ __forceinline__ float2 unpack_f16(uint32_t v) {
    __half2 h = *reinterpret_cast<__half2*>(&v);
    return __half22float2(h);
}

// ---------------- split helpers ----------------
__device__ __forceinline__ void split1h(float f, __half& h, __half& l) {
    h = __float2half_rn(f);
    l = __float2half_rn(f - __half2float(h));
}

// fp32 -> single f16 (A-side operands)
__global__ __launch_bounds__(256)
void conv_rows(const float* __restrict__ in, __half* __restrict__ hi, int n4)
{
    int i = blockIdx.x * 256 + threadIdx.x;
    if (i >= n4) return;
    float4 v = ((const float4*)in)[i];
    uint32_t* hp = (uint32_t*)hi;
    hp[2 * i]     = pack_f16(v.x, v.y);
    hp[2 * i + 1] = pack_f16(v.z, v.w);
}

// W [K][N] fp32 -> B [N][K] f16 hi/lo (transpose + split)
__global__ __launch_bounds__(256)
void split_transpose(const float* __restrict__ W, __half* __restrict__ Bh,
                     __half* __restrict__ Bl, int K, int N)
{
    __shared__ float ts[32][33];
    int n0 = blockIdx.x * 32, k0 = blockIdx.y * 32;
    int tx = threadIdx.x, ty = threadIdx.y;  // (32, 8)
#pragma unroll
    for (int i = 0; i < 4; i++)
        ts[ty + i * 8][tx] = W[(size_t)(k0 + ty + i * 8) * N + n0 + tx];
    __syncthreads();
#pragma unroll
    for (int i = 0; i < 4; i++) {
        float f = ts[tx][ty + i * 8];
        __half h, l;
        split1h(f, h, l);
        size_t o = (size_t)(n0 + ty + i * 8) * K + k0 + tx;
        Bh[o] = h;
        Bl[o] = l;
    }
}

// ============================================================
// mma.sync 2-term f16 GEMM: C = A(f16) @ (Bhi+Blo)^T + bias.
// CTA tile 128(M) x 256(N), BK=32, 8 warps (2x4), warp 64x64,
// 3-stage cp.async, 1 CTA/SM.
// Stage layout: A[128][32] 8KB | Bh[256][32] 16KB | Bl 16KB.
// SPLIT=true: write f16 hi/lo outputs. Else fp32 (+residual).
// ============================================================
#define STAGE_BYTES 40960
#define GSTAGES 3
#define GSM_TOTAL (GSTAGES * STAGE_BYTES)   // 122880

template<bool RES, bool SPLIT>
__global__ __launch_bounds__(256, 1)
void mma_gemm(const __half* __restrict__ A,
              const __half* __restrict__ Bh, const __half* __restrict__ Bl,
              const float* __restrict__ bias, const float* __restrict__ res,
              float* __restrict__ C,
              __half* __restrict__ Oh, __half* __restrict__ Ol,
              int N, int K)
{
    extern __shared__ __align__(1024) char smem[];
    const uint32_t sb = smem_u32(smem);
    const int tid  = threadIdx.x;
    const int lane = tid & 31;
    const int warp = tid >> 5;
    const int wm = warp >> 2;            // 0..1 (M, 64 rows)
    const int wn = warp & 3;             // 0..3 (N, 64 cols)
    const int row0 = blockIdx.x * 128;   // M fast-varying -> B tiles L2-resident
    const int col0 = blockIdx.y * 256;

    const int aRow = wm * 64 + (lane & 15);
    const uint32_t aSw = (uint32_t)((aRow >> 1) & 3);
    const uint32_t aCH = (uint32_t)(lane >> 4);
    const int bRow = wn * 64 + (((lane >> 4) & 1) << 3) + (lane & 7);
    const uint32_t bSw = (uint32_t)((bRow >> 1) & 3);
    const uint32_t bCH = (uint32_t)((lane >> 3) & 1);

    float acc[4][8][4];
#pragma unroll
    for (int mt = 0; mt < 4; mt++)
#pragma unroll
        for (int nt = 0; nt < 8; nt++)
#pragma unroll
            for (int e = 0; e < 4; e++) acc[mt][nt][e] = 0.f;

    // cp.async map: thread -> row (tid>>2), chunk (tid&3); 64 rows/pass.
    // Swizzle offset repeats every 8 rows, so +64-row pass = +4096 bytes.
    const int ldRowA = row0 + (tid >> 2);
    const int ldRowB = col0 + (tid >> 2);
    const int ldC    = tid & 3;
    const uint32_t ldSw = ((uint32_t)(tid >> 2) * 64) ^
                          (((uint32_t)ldC ^ (((uint32_t)(tid >> 2) >> 1) & 3)) << 4);

    const int NK = K / 32;

    auto load_stage = [&](int s, int k0) {
        uint32_t base = sb + (uint32_t)s * STAGE_BYTES;
        const __half* gA  = A  + (size_t)ldRowA * K + k0 + ldC * 8;
        const __half* gB0 = Bh + (size_t)ldRowB * K + k0 + ldC * 8;
        const __half* gB1 = Bl + (size_t)ldRowB * K + k0 + ldC * 8;
        const size_t off64 = (size_t)64 * K;
        // A: 128 rows (2 passes)
        cp_async16(base + ldSw,          gA);
        cp_async16(base + ldSw + 4096,   gA + off64);
        // Bh: 256 rows (4 passes) at +8192
#pragma unroll
        for (int i = 0; i < 4; i++)
            cp_async16(base + 8192 + ldSw + i * 4096u, gB0 + i * off64);
        // Bl: 256 rows at +24576
#pragma unroll
        for (int i = 0; i < 4; i++)
            cp_async16(base + 24576 + ldSw + i * 4096u, gB1 + i * off64);
    };

    load_stage(0, 0);  cp_commit();
    load_stage(1, 32); cp_commit();

    int st = 0;
    for (int kt = 0; kt < NK; kt++) {
        cp_wait1();
        __syncthreads();

        uint32_t base = sb + (uint32_t)st * STAGE_BYTES;
        uint32_t aB   = base +         (uint32_t)aRow * 64;
        uint32_t bHiB = base + 8192  + (uint32_t)bRow * 64;
        uint32_t bLoB = base + 24576 + (uint32_t)bRow * 64;

#pragma unroll
        for (int k = 0; k < 2; k++) {
            const uint32_t ka = ((2u * k + aCH) ^ aSw) << 4;
            const uint32_t kb = ((2u * k + bCH) ^ bSw) << 4;
            // B fragments: 4 n16-tiles x (hi,lo) -> 32 regs
            uint32_t bhi[4][4], blo[4][4];
#pragma unroll
            for (int p = 0; p < 4; p++) {
                ldsm4(bhi[p], bHiB + p * 1024 + kb);
                ldsm4(blo[p], bLoB + p * 1024 + kb);
            }
#pragma unroll
            for (int mt = 0; mt < 4; mt++) {
                uint32_t av[4];
                ldsm4(av, aB + mt * 1024 + ka);
#pragma unroll
                for (int nt = 0; nt < 8; nt++) {
                    mma_f16(acc[mt][nt], av, &bhi[nt >> 1][(nt & 1) * 2]);
                    mma_f16(acc[mt][nt], av, &blo[nt >> 1][(nt & 1) * 2]);
                }
            }
        }

        if (kt + 2 < NK) load_stage((st + 2) % GSTAGES, (kt + 2) * 32);
        cp_commit();
        st = (st + 1) % GSTAGES;
    }

    const int g  = lane >> 2;
    const int i4 = lane & 3;
#pragma unroll
    for (int mt = 0; mt < 4; mt++) {
        int r = row0 + wm * 64 + mt * 16 + g;
#pragma unroll
        for (int nt = 0; nt < 8; nt++) {
            int c = col0 + wn * 64 + nt * 8 + i4 * 2;
            float2 bv = *(const float2*)(bias + c);
            size_t o0 = (size_t)r * N + c;
            size_t o1 = (size_t)(r + 8) * N + c;
            float v00 = acc[mt][nt][0] + bv.x, v01 = acc[mt][nt][1] + bv.y;
            float v10 = acc[mt][nt][2] + bv.x, v11 = acc[mt][nt][3] + bv.y;
            if (SPLIT) {
                uint32_t h0 = pack_f16(v00, v01);
                uint32_t h1 = pack_f16(v10, v11);
                float2 u0 = unpack_f16(h0);
                float2 u1 = unpack_f16(h1);
                uint32_t l0 = pack_f16(v00 - u0.x, v01 - u0.y);
                uint32_t l1 = pack_f16(v10 - u1.x, v11 - u1.y);
                *(uint32_t*)(Oh + o0) = h0;
                *(uint32_t*)(Ol + o0) = l0;
                *(uint32_t*)(Oh + o1) = h1;
                *(uint32_t*)(Ol + o1) = l1;
            } else {
                float2 v0, v1;
                v0.x = v00; v0.y = v01;
                v1.x = v10; v1.y = v11;
                if (RES) {
                    float2 r0 = *(const float2*)(res + o0);
                    float2 r1 = *(const float2*)(res + o1);
                    v0.x += r0.x; v0.y += r0.y;
                    v1.x += r1.x; v1.y += r1.y;
                }
                *(float2*)(C + o0) = v0;
                *(float2*)(C + o1) = v1;
            }
        }
    }
}

// ============================================================
// FA2-style attention, mma.sync 2-term f16 (round-9 proven).
// ============================================================
#define AQ_OFF   0u
#define ASTG_OFF 32768u
#define ASTG_SZ  65536u
#define ATTN_SMEM (32768 + 2 * 65536)   // 163840 B

__global__ __launch_bounds__(256, 1)
void attn_mma(const __half* __restrict__ QKVh,
              const __half* __restrict__ QKVl,
              const float* __restrict__ alibi,
              __half* __restrict__ Ch, int batch)
{
    extern __shared__ __align__(1024) char sm[];
    const uint32_t sb = smem_u32(sm);
    const uint32_t Qs = sb + AQ_OFF;

    const int qt   = (int)gridDim.x - 1 - (int)blockIdx.x;  // heavy tiles first
    const int h    = blockIdx.y;
    const int bh   = batch * 32 + h;
    const int tid  = threadIdx.x;
    const int lane = tid & 31;
    const int warp = tid >> 5;

    const size_t rowbase = (size_t)batch * S_;
    const int qcol = h * 384;
    const float* al = alibi + (size_t)bh * S_;
    const float inv = 0.08838834764831845f;

    const int ldR  = tid >> 4;
    const int ldCk = tid & 15;

    auto load_q = [&]() {
#pragma unroll
        for (int i = 0; i < 8; i++) {
            int r = i * 16 + ldR;
            uint32_t dst = (uint32_t)r * 256 +
                (((uint32_t)ldCk ^ ((uint32_t)r & 7)) << 4);
            size_t goff = (rowbase + qt * 128 + r) * NQKV_ + qcol + ldCk * 8;
            cp_async16(Qs + dst, QKVh + goff);
        }
    };
    auto load_kv = [&](int j, int slot) {
        uint32_t stg = sb + ASTG_OFF + (uint32_t)slot * ASTG_SZ;
#pragma unroll
        for (int i = 0; i < 4; i++) {
            int r = i * 16 + ldR;
            uint32_t dst = (uint32_t)r * 256 +
                (((uint32_t)ldCk ^ ((uint32_t)r & 7)) << 4);
            size_t goff = (rowbase + j * 64 + r) * NQKV_ + qcol + ldCk * 8;
            cp_async16(stg +         dst, QKVh + goff + 128);   // Khi
            cp_async16(stg + 16384 + dst, QKVl + goff + 128);   // Klo
            cp_async16(stg + 32768 + dst, QKVh + goff + 256);   // Vhi
            cp_async16(stg + 49152 + dst, QKVl + goff + 256);   // Vlo
        }
    };

    const int jmax = 2 * qt + 1;
    load_q(); load_kv(0, 0); cp_commit();
    if (jmax >= 1) load_kv(1, 1);
    cp_commit();

    const int aRow = warp * 16 + (lane & 15);
    const uint32_t aChH = (uint32_t)(lane >> 4);
    const int bRowBase = (((lane >> 4) & 1) << 3) + (lane & 7);
    const uint32_t bChH = (uint32_t)((lane >> 3) & 1);
    const int vTok = (lane & 7) + (lane & 8);
    const int vD   = (lane >> 4) << 3;

    const int g  = lane >> 2;
    const int c2 = (lane & 3) * 2;
    const int qg0 = qt * 128 + warp * 16 + g;

    float O[16][4];
#pragma unroll
    for (int n = 0; n < 16; n++)
#pragma unroll
        for (int e = 0; e < 4; e++) O[n][e] = 0.f;
    float m0 = -1e30f, m1 = -1e30f, l0 = 0.f, l1 = 0.f;

    for (int j = 0; j <= jmax; j++) {
        cp_wait1();
        __syncthreads();

        uint32_t stg = sb + ASTG_OFF + (uint32_t)(j & 1) * ASTG_SZ;
        const uint32_t Kh = stg, Kl = stg + 16384;
        const uint32_t Vh = stg + 32768, Vl = stg + 49152;

        float S[8][4];
#pragma unroll
        for (int n = 0; n < 8; n++)
#pragma unroll
            for (int e = 0; e < 4; e++) S[n][e] = 0.f;

#pragma unroll
        for (int ks = 0; ks < 8; ks++) {
            uint32_t aOff = (uint32_t)aRow * 256 +
                (((2u * ks + aChH) ^ ((uint32_t)aRow & 7)) << 4);
            uint32_t av[4];
            ldsm4(av, Qs + aOff);
#pragma unroll
            for (int p = 0; p < 4; p++) {
                int bRow = p * 16 + bRowBase;
                uint32_t bOff = (uint32_t)bRow * 256 +
                    (((2u * ks + bChH) ^ ((uint32_t)bRow & 7)) << 4);
                uint32_t bhi[4], blo[4];
                ldsm4(bhi, Kh + bOff);
                ldsm4(blo, Kl + bOff);
#pragma unroll
                for (int q2 = 0; q2 < 2; q2++) {
                    int nt = p * 2 + q2;
                    mma_f16(S[nt], av, &bhi[q2 * 2]);
                    mma_f16(S[nt], av, &blo[q2 * 2]);
                }
            }
        }

        const bool diag = (j * 64 + 63 > qt * 128 + warp * 16);
#pragma unroll
        for (int nt = 0; nt < 8; nt++) {
            float2 a = *(const float2*)(al + j * 64 + nt * 8 + c2);
            S[nt][0] = S[nt][0] * inv + a.x;
            S[nt][1] = S[nt][1] * inv + a.y;
            S[nt][2] = S[nt][2] * inv + a.x;
            S[nt][3] = S[nt][3] * inv + a.y;
            if (diag) {
                int kg = j * 64 + nt * 8 + c2;
                if (kg     > qg0)     S[nt][0] = -1e30f;
                if (kg + 1 > qg0)     S[nt][1] = -1e30f;
                if (kg     > qg0 + 8) S[nt][2] = -1e30f;
                if (kg + 1 > qg0 + 8) S[nt][3] = -1e30f;
            }
        }

        float mx0 = -1e30f, mx1 = -1e30f;
#pragma unroll
        for (int nt = 0; nt < 8; nt++) {
            mx0 = fmaxf(mx0, fmaxf(S[nt][0], S[nt][1]));
            mx1 = fmaxf(mx1, fmaxf(S[nt][2], S[nt][3]));
        }
        mx0 = fmaxf(mx0, __shfl_xor_sync(0xffffffffu, mx0, 1));
        mx0 = fmaxf(mx0, __shfl_xor_sync(0xffffffffu, mx0, 2));
        mx1 = fmaxf(mx1, __shfl_xor_sync(0xffffffffu, mx1, 1));
        mx1 = fmaxf(mx1, __shfl_xor_sync(0xffffffffu, mx1, 2));
        float mn0 = fmaxf(m0, mx0), mn1 = fmaxf(m1, mx1);
        float sf0 = __expf(m0 - mn0), sf1 = __expf(m1 - mn1);
        float sum0 = 0.f, sum1 = 0.f;
#pragma unroll
        for (int nt = 0; nt < 8; nt++) {
            S[nt][0] = __expf(S[nt][0] - mn0); sum0 += S[nt][0];
            S[nt][1] = __expf(S[nt][1] - mn0); sum0 += S[nt][1];
            S[nt][2] = __expf(S[nt][2] - mn1); sum1 += S[nt][2];
            S[nt][3] = __expf(S[nt][3] - mn1); sum1 += S[nt][3];
        }
        sum0 += __shfl_xor_sync(0xffffffffu, sum0, 1);
        sum0 += __shfl_xor_sync(0xffffffffu, sum0, 2);
        sum1 += __shfl_xor_sync(0xffffffffu, sum1, 1);
        sum1 += __shfl_xor_sync(0xffffffffu, sum1, 2);
        l0 = l0 * sf0 + sum0; m0 = mn0;
        l1 = l1 * sf1 + sum1; m1 = mn1;
#pragma unroll
        for (int n = 0; n < 16; n++) {
            O[n][0] *= sf0; O[n][1] *= sf0;
            O[n][2] *= sf1; O[n][3] *= sf1;
        }

        // O += P V  (P single f16; V hi+lo)
#pragma unroll
        for (int ks = 0; ks < 4; ks++) {
            uint32_t pa[4];
            pa[0] = pack_f16(S[2 * ks][0],     S[2 * ks][1]);
            pa[1] = pack_f16(S[2 * ks][2],     S[2 * ks][3]);
            pa[2] = pack_f16(S[2 * ks + 1][0], S[2 * ks + 1][1]);
            pa[3] = pack_f16(S[2 * ks + 1][2], S[2 * ks + 1][3]);
            int tok = ks * 16 + vTok;
            uint32_t tRow = (uint32_t)tok * 256;
            uint32_t tSw  = (uint32_t)tok & 7;
#pragma unroll
            for (int nt16 = 0; nt16 < 8; nt16++) {
                int d = nt16 * 16 + vD;
                uint32_t vOff = tRow + ((((uint32_t)d >> 3) ^ tSw) << 4);
                uint32_t bvh[4], bvl[4];
                ldsm4t(bvh, Vh + vOff);
                ldsm4t(bvl, Vl + vOff);
                mma_f16(O[nt16 * 2],     pa, &bvh[0]);
                mma_f16(O[nt16 * 2 + 1], pa, &bvh[2]);
                mma_f16(O[nt16 * 2],     pa, &bvl[0]);
                mma_f16(O[nt16 * 2 + 1], pa, &bvl[2]);
            }
        }

        __syncthreads();
        if (j + 2 <= jmax) load_kv(j + 2, j & 1);
        cp_commit();
    }

    // epilogue: ctx = O / l, single f16 (A-side of dense GEMM)
    float il0 = 1.f / l0, il1 = 1.f / l1;
    size_t r0 = rowbase + qt * 128 + warp * 16 + g;
    size_t r1 = r0 + 8;
#pragma unroll
    for (int n = 0; n < 16; n++) {
        int col = h * 128 + n * 8 + c2;
        *(uint32_t*)(Ch + r0 * H_ + col) = pack_f16(O[n][0] * il0, O[n][1] * il0);
        *(uint32_t*)(Ch + r1 * H_ + col) = pack_f16(O[n][2] * il1, O[n][3] * il1);
    }
}

// ============================================================
// Launch: serial splits + QKV, then b0/b1 overlap (proven)
// ============================================================
extern "C" void kernel_launch(void* const* d_in, const int* in_sizes, int n_in,
                              void* d_out, int out_size)
{
    const float* hidden   = (const float*)d_in[0];
    const float* residual = (const float*)d_in[1];
    const float* alibi    = (const float*)d_in[2];
    const float* Wqkv     = (const float*)d_in[4];
    const float* bqkv     = (const float*)d_in[5];
    const float* Wd       = (const float*)d_in[6];
    const float* bd       = (const float*)d_in[7];
    float* out = (float*)d_out;

    void* p;
    cudaGetSymbolAddress(&p, g_QKVh); __half* QKVh = (__half*)p;
    cudaGetSymbolAddress(&p, g_QKVl); __half* QKVl = (__half*)p;
    cudaGetSymbolAddress(&p, g_Ah);   __half* Ah   = (__half*)p;
    cudaGetSymbolAddress(&p, g_Bqh);  __half* Bqh  = (__half*)p;
    cudaGetSymbolAddress(&p, g_Bql);  __half* Bql  = (__half*)p;
    cudaGetSymbolAddress(&p, g_Bdh);  __half* Bdh  = (__half*)p;
    cudaGetSymbolAddress(&p, g_Bdl);  __half* Bdl  = (__half*)p;
    cudaGetSymbolAddress(&p, g_Ch);   __half* Ch   = (__half*)p;

    cudaFuncSetAttribute(attn_mma, cudaFuncAttributeMaxDynamicSharedMemorySize, ATTN_SMEM);
    cudaFuncSetAttribute(mma_gemm<false, true>,
                         cudaFuncAttributeMaxDynamicSharedMemorySize, GSM_TOTAL);
    cudaFuncSetAttribute(mma_gemm<true, false>,
                         cudaFuncAttributeMaxDynamicSharedMemorySize, GSM_TOTAL);

    cudaStream_t s1;
    cudaStreamCreateWithFlags(&s1, cudaStreamNonBlocking);
    cudaEvent_t evQ, evE;
    cudaEventCreateWithFlags(&evQ, cudaEventDisableTiming);
    cudaEventCreateWithFlags(&evE, cudaEventDisableTiming);

    const size_t half = (size_t)S_ * H_;   // 1024 rows

    // serial: converts/splits then QKV projection (split f16 output)
    conv_rows<<<(M_ * H_ / 4 + 255) / 256, 256>>>(hidden, Ah, M_ * H_ / 4);
    split_transpose<<<dim3(NQKV_ / 32, H_ / 32), dim3(32, 8)>>>(Wqkv, Bqh, Bql, H_, NQKV_);
    split_transpose<<<dim3(H_ / 32, H_ / 32), dim3(32, 8)>>>(Wd, Bdh, Bdl, H_, H_);
    mma_gemm<false, true><<<dim3(M_ / 128, NQKV_ / 256), 256, GSM_TOTAL>>>(
        Ah, Bqh, Bql, bqkv, nullptr, nullptr, QKVh, QKVl, NQKV_, H_);
    cudaEventRecord(evQ, 0);

    // s1: batch-1 attention then batch-1 dense
    cudaStreamWaitEvent(s1, evQ, 0);
    attn_mma<<<dim3(8, 32), 256, ATTN_SMEM, s1>>>(QKVh, QKVl, alibi, Ch, 1);
    mma_gemm<true, false><<<dim3(8, H_ / 256), 256, GSM_TOTAL, s1>>>(
        Ch + half, Bdh, Bdl, bd, residual + half, out + half,
        nullptr, nullptr, H_, H_);
    cudaEventRecord(evE, s1);

    // main: batch-0 attention then batch-0 dense
    attn_mma<<<dim3(8, 32), 256, ATTN_SMEM>>>(QKVh, QKVl, alibi, Ch, 0);
    mma_gemm<true, false><<<dim3(8, H_ / 256), 256, GSM_TOTAL>>>(
        Ch, Bdh, Bdl, bd, residual, out, nullptr, nullptr, H_, H_);

    // join
    cudaStreamWaitEvent(0, evE, 0);
}

// round 12
// speedup vs baseline: 2.0630x; 2.0630x over previous
#include <cuda_runtime.h>
#include <cuda_fp16.h>
#include <stdint.h>
#include <math.h>

// Problem constants
#define B_    2
#define S_    1024
#define H_    4096
#define NH_   32
#define HD_   128
#define M_    2048
#define NQKV_ 12288

// ---------------- device scratch (no runtime allocation) ----------------
__device__ __half g_QKV[(size_t)M_ * NQKV_];
__device__ __half g_Ah[(size_t)M_ * H_];
__device__ __half g_Bq[(size_t)NQKV_ * H_];
__device__ __half g_Bd[(size_t)H_ * H_];
__device__ __half g_Ch[(size_t)M_ * H_];

// ---------------- PTX helpers (portable, non-'a' features only) ----------------
__device__ __forceinline__ uint32_t smem_u32(const void* p) {
    uint32_t a;
    asm("{ .reg .u64 t; cvta.to.shared.u64 t, %1; cvt.u32.u64 %0, t; }" : "=r"(a) : "l"(p));
    return a;
}
__device__ __forceinline__ void cp_async16(uint32_t dst_smem, const void* src) {
    asm volatile("cp.async.cg.shared.global [%0], [%1], 16;"
                 :: "r"(dst_smem), "l"(src) : "memory");
}
__device__ __forceinline__ void cp_commit() {
    asm volatile("cp.async.commit_group;" ::: "memory");
}
__device__ __forceinline__ void cp_wait1() {
    asm volatile("cp.async.wait_group 1;" ::: "memory");
}
__device__ __forceinline__ void ldsm4(uint32_t* r, uint32_t addr) {
    asm volatile("ldmatrix.sync.aligned.m8n8.x4.shared.b16 {%0,%1,%2,%3}, [%4];"
                 : "=r"(r[0]), "=r"(r[1]), "=r"(r[2]), "=r"(r[3]) : "r"(addr));
}
__device__ __forceinline__ void ldsm4t(uint32_t* r, uint32_t addr) {
    asm volatile("ldmatrix.sync.aligned.m8n8.x4.trans.shared.b16 {%0,%1,%2,%3}, [%4];"
                 : "=r"(r[0]), "=r"(r[1]), "=r"(r[2]), "=r"(r[3]) : "r"(addr));
}
__device__ __forceinline__ void mma_f16(float* d, const uint32_t* a, const uint32_t* b) {
    asm volatile(
        "mma.sync.aligned.m16n8k16.row.col.f32.f16.f16.f32 "
        "{%0,%1,%2,%3}, {%4,%5,%6,%7}, {%8,%9}, {%0,%1,%2,%3};"
        : "+f"(d[0]), "+f"(d[1]), "+f"(d[2]), "+f"(d[3])
        : "r"(a[0]), "r"(a[1]), "r"(a[2]), "r"(a[3]), "r"(b[0]), "r"(b[1]));
}
__device__ __forceinline__ uint32_t pack_f16(float lo, float hi) {
    uint32_t r;
    asm("cvt.rn.f16x2.f32 %0, %1, %2;" : "=r"(r) : "f"(hi), "f"(lo));
    return r;
}

// ---------------- conversion kernels ----------------
// fp32 -> f16 rows
__global__ __launch_bounds__(256)
void conv_rows(const float* __restrict__ in, __half* __restrict__ out, int n4)
{
    int i = blockIdx.x * 256 + threadIdx.x;
    if (i >= n4) return;
    float4 v = ((const float4*)in)[i];
    uint32_t* hp = (uint32_t*)out;
    hp[2 * i]     = pack_f16(v.x, v.y);
    hp[2 * i + 1] = pack_f16(v.z, v.w);
}

// W [K][N] fp32 -> Bt [N][K] f16 (transpose + convert)
__global__ __launch_bounds__(256)
void conv_transpose(const float* __restrict__ W, __half* __restrict__ Bt, int K, int N)
{
    __shared__ float ts[32][33];
    int n0 = blockIdx.x * 32, k0 = blockIdx.y * 32;
    int tx = threadIdx.x, ty = threadIdx.y;  // (32, 8)
#pragma unroll
    for (int i = 0; i < 4; i++)
        ts[ty + i * 8][tx] = W[(size_t)(k0 + ty + i * 8) * N + n0 + tx];
    __syncthreads();
#pragma unroll
    for (int i = 0; i < 4; i++) {
        size_t o = (size_t)(n0 + ty + i * 8) * K + k0 + tx;
        Bt[o] = __float2half_rn(ts[tx][ty + i * 8]);
    }
}

// ============================================================
// mma.sync single-f16 GEMM: C = A @ B^T + bias (+res).
// CTA 128x128, BK=32, 128 threads, 4 warps (2x2), warp 64x64,
// 3-stage cp.async, 2 CTAs/SM (128thr -> 256 regs/thread avail).
// Stage: A[128][32] 8KB | B[128][32] 8KB = 16KB.
// SPLIT=true: write f16 output. Else fp32 (+residual).
// ============================================================
#define STAGE_BYTES 16384
#define GSTAGES 3
#define GSM_TOTAL (GSTAGES * STAGE_BYTES)   // 49152

template<bool RES, bool SPLIT>
__global__ __launch_bounds__(128, 2)
void mma_gemm(const __half* __restrict__ A, const __half* __restrict__ B,
              const float* __restrict__ bias, const float* __restrict__ res,
              float* __restrict__ C, __half* __restrict__ Oh,
              int N, int K)
{
    extern __shared__ __align__(1024) char smem[];
    const uint32_t sb = smem_u32(smem);
    const int tid  = threadIdx.x;
    const int lane = tid & 31;
    const int warp = tid >> 5;           // 0..3
    const int wm = warp >> 1;            // 0..1 (M)
    const int wn = warp & 1;             // 0..1 (N)
    const int row0 = blockIdx.x * 128;   // M fast-varying -> B tiles L2-resident
    const int col0 = blockIdx.y * 128;

    const int aRow = wm * 64 + (lane & 15);
    const uint32_t aSw = (uint32_t)((aRow >> 1) & 3);
    const uint32_t aCH = (uint32_t)(lane >> 4);
    const int bRow = wn * 64 + (((lane >> 4) & 1) << 3) + (lane & 7);
    const uint32_t bSw = (uint32_t)((bRow >> 1) & 3);
    const uint32_t bCH = (uint32_t)((lane >> 3) & 1);

    float acc[4][8][4];
#pragma unroll
    for (int mt = 0; mt < 4; mt++)
#pragma unroll
        for (int nt = 0; nt < 8; nt++)
#pragma unroll
            for (int e = 0; e < 4; e++) acc[mt][nt][e] = 0.f;

    // cp.async map: 128 threads, row = tid>>2 (0..31), chunk = tid&3.
    // 4 passes of 32 rows each; swizzle period 8 rows -> +2048B per pass.
    const int ldRow = tid >> 2;
    const int ldC   = tid & 3;
    const uint32_t ldSw = ((uint32_t)ldRow * 64) ^
                          (((uint32_t)ldC ^ (((uint32_t)ldRow >> 1) & 3)) << 4);

    const int NK = K / 32;

    auto load_stage = [&](int s, int k0) {
        uint32_t base = sb + (uint32_t)s * STAGE_BYTES;
        const __half* gA = A + (size_t)(row0 + ldRow) * K + k0 + ldC * 8;
        const __half* gB = B + (size_t)(col0 + ldRow) * K + k0 + ldC * 8;
        const size_t off32 = (size_t)32 * K;
#pragma unroll
        for (int i = 0; i < 4; i++)
            cp_async16(base + ldSw + i * 2048u, gA + i * off32);
#pragma unroll
        for (int i = 0; i < 4; i++)
            cp_async16(base + 8192 + ldSw + i * 2048u, gB + i * off32);
    };

    load_stage(0, 0);  cp_commit();
    load_stage(1, 32); cp_commit();

    int st = 0;
    for (int kt = 0; kt < NK; kt++) {
        cp_wait1();
        __syncthreads();

        uint32_t base = sb + (uint32_t)st * STAGE_BYTES;
        uint32_t aB = base +        (uint32_t)aRow * 64;
        uint32_t bB = base + 8192 + (uint32_t)bRow * 64;

#pragma unroll
        for (int k = 0; k < 2; k++) {
            const uint32_t ka = ((2u * k + aCH) ^ aSw) << 4;
            const uint32_t kb = ((2u * k + bCH) ^ bSw) << 4;
            uint32_t bf[4][4];
#pragma unroll
            for (int p = 0; p < 4; p++)
                ldsm4(bf[p], bB + p * 1024 + kb);
#pragma unroll
            for (int mt = 0; mt < 4; mt++) {
                uint32_t av[4];
                ldsm4(av, aB + mt * 1024 + ka);
#pragma unroll
                for (int nt = 0; nt < 8; nt++)
                    mma_f16(acc[mt][nt], av, &bf[nt >> 1][(nt & 1) * 2]);
            }
        }

        if (kt + 2 < NK) load_stage((st + 2) % GSTAGES, (kt + 2) * 32);
        cp_commit();
        st = (st + 1) % GSTAGES;
    }

    const int g  = lane >> 2;
    const int i4 = lane & 3;
#pragma unroll
    for (int mt = 0; mt < 4; mt++) {
        int r = row0 + wm * 64 + mt * 16 + g;
#pragma unroll
        for (int nt = 0; nt < 8; nt++) {
            int c = col0 + wn * 64 + nt * 8 + i4 * 2;
            float2 bv = *(const float2*)(bias + c);
            size_t o0 = (size_t)r * N + c;
            size_t o1 = (size_t)(r + 8) * N + c;
            float v00 = acc[mt][nt][0] + bv.x, v01 = acc[mt][nt][1] + bv.y;
            float v10 = acc[mt][nt][2] + bv.x, v11 = acc[mt][nt][3] + bv.y;
            if (SPLIT) {
                *(uint32_t*)(Oh + o0) = pack_f16(v00, v01);
                *(uint32_t*)(Oh + o1) = pack_f16(v10, v11);
            } else {
                float2 v0, v1;
                v0.x = v00; v0.y = v01;
                v1.x = v10; v1.y = v11;
                if (RES) {
                    float2 r0 = *(const float2*)(res + o0);
                    float2 r1 = *(const float2*)(res + o1);
                    v0.x += r0.x; v0.y += r0.y;
                    v1.x += r1.x; v1.y += r1.y;
                }
                *(float2*)(C + o0) = v0;
                *(float2*)(C + o1) = v1;
            }
        }
    }
}

// ============================================================
// FA2-style attention, mma.sync single-f16.
// CTA: q-tile 128 (8 warps x m16), kv-tile 64, double-buffered.
// smem: Q 32K | stage{0,1}: K 16K + V 16K = 32K each.
// ============================================================
#define AQ_OFF   0u
#define ASTG_OFF 32768u
#define ASTG_SZ  32768u
#define ATTN_SMEM (32768 + 2 * 32768)   // 98304 B

__global__ __launch_bounds__(256, 1)
void attn_mma(const __half* __restrict__ QKV,
              const float* __restrict__ alibi,
              __half* __restrict__ Ch, int batch)
{
    extern __shared__ __align__(1024) char sm[];
    const uint32_t sb = smem_u32(sm);
    const uint32_t Qs = sb + AQ_OFF;

    const int qt   = (int)gridDim.x - 1 - (int)blockIdx.x;  // heavy tiles first
    const int h    = blockIdx.y;
    const int bh   = batch * 32 + h;
    const int tid  = threadIdx.x;
    const int lane = tid & 31;
    const int warp = tid >> 5;

    const size_t rowbase = (size_t)batch * S_;
    const int qcol = h * 384;
    const float* al = alibi + (size_t)bh * S_;
    const float inv = 0.08838834764831845f;

    const int ldR  = tid >> 4;
    const int ldCk = tid & 15;

    auto load_q = [&]() {
#pragma unroll
        for (int i = 0; i < 8; i++) {
            int r = i * 16 + ldR;
            uint32_t dst = (uint32_t)r * 256 +
                (((uint32_t)ldCk ^ ((uint32_t)r & 7)) << 4);
            size_t goff = (rowbase + qt * 128 + r) * NQKV_ + qcol + ldCk * 8;
            cp_async16(Qs + dst, QKV + goff);
        }
    };
    auto load_kv = [&](int j, int slot) {
        uint32_t stg = sb + ASTG_OFF + (uint32_t)slot * ASTG_SZ;
#pragma unroll
        for (int i = 0; i < 4; i++) {
            int r = i * 16 + ldR;
            uint32_t dst = (uint32_t)r * 256 +
                (((uint32_t)ldCk ^ ((uint32_t)r & 7)) << 4);
            size_t goff = (rowbase + j * 64 + r) * NQKV_ + qcol + ldCk * 8;
            cp_async16(stg +         dst, QKV + goff + 128);   // K
            cp_async16(stg + 16384 + dst, QKV + goff + 256);   // V
        }
    };

    const int jmax = 2 * qt + 1;
    load_q(); load_kv(0, 0); cp_commit();
    if (jmax >= 1) load_kv(1, 1);
    cp_commit();

    const int aRow = warp * 16 + (lane & 15);
    const uint32_t aChH = (uint32_t)(lane >> 4);
    const int bRowBase = (((lane >> 4) & 1) << 3) + (lane & 7);
    const uint32_t bChH = (uint32_t)((lane >> 3) & 1);
    const int vTok = (lane & 7) + (lane & 8);
    const int vD   = (lane >> 4) << 3;

    const int g  = lane >> 2;
    const int c2 = (lane & 3) * 2;
    const int qg0 = qt * 128 + warp * 16 + g;

    float O[16][4];
#pragma unroll
    for (int n = 0; n < 16; n++)
#pragma unroll
        for (int e = 0; e < 4; e++) O[n][e] = 0.f;
    float m0 = -1e30f, m1 = -1e30f, l0 = 0.f, l1 = 0.f;

    for (int j = 0; j <= jmax; j++) {
        cp_wait1();
        __syncthreads();

        uint32_t stg = sb + ASTG_OFF + (uint32_t)(j & 1) * ASTG_SZ;
        const uint32_t Ks = stg, Vs = stg + 16384;

        float S[8][4];
#pragma unroll
        for (int n = 0; n < 8; n++)
#pragma unroll
            for (int e = 0; e < 4; e++) S[n][e] = 0.f;

#pragma unroll
        for (int ks = 0; ks < 8; ks++) {
            uint32_t aOff = (uint32_t)aRow * 256 +
                (((2u * ks + aChH) ^ ((uint32_t)aRow & 7)) << 4);
            uint32_t av[4];
            ldsm4(av, Qs + aOff);
#pragma unroll
            for (int p = 0; p < 4; p++) {
                int bRow = p * 16 + bRowBase;
                uint32_t bOff = (uint32_t)bRow * 256 +
                    (((2u * ks + bChH) ^ ((uint32_t)bRow & 7)) << 4);
                uint32_t bk[4];
                ldsm4(bk, Ks + bOff);
                mma_f16(S[p * 2],     av, &bk[0]);
                mma_f16(S[p * 2 + 1], av, &bk[2]);
            }
        }

        const bool diag = (j * 64 + 63 > qt * 128 + warp * 16);
#pragma unroll
        for (int nt = 0; nt < 8; nt++) {
            float2 a = *(const float2*)(al + j * 64 + nt * 8 + c2);
            S[nt][0] = S[nt][0] * inv + a.x;
            S[nt][1] = S[nt][1] * inv + a.y;
            S[nt][2] = S[nt][2] * inv + a.x;
            S[nt][3] = S[nt][3] * inv + a.y;
            if (diag) {
                int kg = j * 64 + nt * 8 + c2;
                if (kg     > qg0)     S[nt][0] = -1e30f;
                if (kg + 1 > qg0)     S[nt][1] = -1e30f;
                if (kg     > qg0 + 8) S[nt][2] = -1e30f;
                if (kg + 1 > qg0 + 8) S[nt][3] = -1e30f;
            }
        }

        float mx0 = -1e30f, mx1 = -1e30f;
#pragma unroll
        for (int nt = 0; nt < 8; nt++) {
            mx0 = fmaxf(mx0, fmaxf(S[nt][0], S[nt][1]));
            mx1 = fmaxf(mx1, fmaxf(S[nt][2], S[nt][3]));
        }
        mx0 = fmaxf(mx0, __shfl_xor_sync(0xffffffffu, mx0, 1));
        mx0 = fmaxf(mx0, __shfl_xor_sync(0xffffffffu, mx0, 2));
        mx1 = fmaxf(mx1, __shfl_xor_sync(0xffffffffu, mx1, 1));
        mx1 = fmaxf(mx1, __shfl_xor_sync(0xffffffffu, mx1, 2));
        float mn0 = fmaxf(m0, mx0), mn1 = fmaxf(m1, mx1);
        float sf0 = __expf(m0 - mn0), sf1 = __expf(m1 - mn1);
        float sum0 = 0.f, sum1 = 0.f;
#pragma unroll
        for (int nt = 0; nt < 8; nt++) {
            S[nt][0] = __expf(S[nt][0] - mn0); sum0 += S[nt][0];
            S[nt][1] = __expf(S[nt][1] - mn0); sum0 += S[nt][1];
            S[nt][2] = __expf(S[nt][2] - mn1); sum1 += S[nt][2];
            S[nt][3] = __expf(S[nt][3] - mn1); sum1 += S[nt][3];
        }
        sum0 += __shfl_xor_sync(0xffffffffu, sum0, 1);
        sum0 += __shfl_xor_sync(0xffffffffu, sum0, 2);
        sum1 += __shfl_xor_sync(0xffffffffu, sum1, 1);
        sum1 += __shfl_xor_sync(0xffffffffu, sum1, 2);
        l0 = l0 * sf0 + sum0; m0 = mn0;
        l1 = l1 * sf1 + sum1; m1 = mn1;
#pragma unroll
        for (int n = 0; n < 16; n++) {
            O[n][0] *= sf0; O[n][1] *= sf0;
            O[n][2] *= sf1; O[n][3] *= sf1;
        }

        // O += P V  (single f16)
#pragma unroll
        for (int ks = 0; ks < 4; ks++) {
            uint32_t pa[4];
            pa[0] = pack_f16(S[2 * ks][0],     S[2 * ks][1]);
            pa[1] = pack_f16(S[2 * ks][2],     S[2 * ks][3]);
            pa[2] = pack_f16(S[2 * ks + 1][0], S[2 * ks + 1][1]);
            pa[3] = pack_f16(S[2 * ks + 1][2], S[2 * ks + 1][3]);
            int tok = ks * 16 + vTok;
            uint32_t tRow = (uint32_t)tok * 256;
            uint32_t tSw  = (uint32_t)tok & 7;
#pragma unroll
            for (int nt16 = 0; nt16 < 8; nt16++) {
                int d = nt16 * 16 + vD;
                uint32_t vOff = tRow + ((((uint32_t)d >> 3) ^ tSw) << 4);
                uint32_t bv[4];
                ldsm4t(bv, Vs + vOff);
                mma_f16(O[nt16 * 2],     pa, &bv[0]);
                mma_f16(O[nt16 * 2 + 1], pa, &bv[2]);
            }
        }

        __syncthreads();
        if (j + 2 <= jmax) load_kv(j + 2, j & 1);
        cp_commit();
    }

    // epilogue: ctx = O / l, single f16 (A-side of dense GEMM)
    float il0 = 1.f / l0, il1 = 1.f / l1;
    size_t r0 = rowbase + qt * 128 + warp * 16 + g;
    size_t r1 = r0 + 8;
#pragma unroll
    for (int n = 0; n < 16; n++) {
        int col = h * 128 + n * 8 + c2;
        *(uint32_t*)(Ch + r0 * H_ + col) = pack_f16(O[n][0] * il0, O[n][1] * il0);
        *(uint32_t*)(Ch + r1 * H_ + col) = pack_f16(O[n][2] * il1, O[n][3] * il1);
    }
}

// ============================================================
// Launch: serial converts + QKV, then b0/b1 overlap (proven)
// ============================================================
extern "C" void kernel_launch(void* const* d_in, const int* in_sizes, int n_in,
                              void* d_out, int out_size)
{
    const float* hidden   = (const float*)d_in[0];
    const float* residual = (const float*)d_in[1];
    const float* alibi    = (const float*)d_in[2];
    const float* Wqkv     = (const float*)d_in[4];
    const float* bqkv     = (const float*)d_in[5];
    const float* Wd       = (const float*)d_in[6];
    const float* bd       = (const float*)d_in[7];
    float* out = (float*)d_out;

    void* p;
    cudaGetSymbolAddress(&p, g_QKV); __half* QKV = (__half*)p;
    cudaGetSymbolAddress(&p, g_Ah);  __half* Ah  = (__half*)p;
    cudaGetSymbolAddress(&p, g_Bq);  __half* Bq  = (__half*)p;
    cudaGetSymbolAddress(&p, g_Bd);  __half* Bd  = (__half*)p;
    cudaGetSymbolAddress(&p, g_Ch);  __half* Ch  = (__half*)p;

    cudaFuncSetAttribute(attn_mma, cudaFuncAttributeMaxDynamicSharedMemorySize, ATTN_SMEM);
    cudaFuncSetAttribute(mma_gemm<false, true>,
                         cudaFuncAttributeMaxDynamicSharedMemorySize, GSM_TOTAL);
    cudaFuncSetAttribute(mma_gemm<true, false>,
                         cudaFuncAttributeMaxDynamicSharedMemorySize, GSM_TOTAL);

    cudaStream_t s1;
    cudaStreamCreateWithFlags(&s1, cudaStreamNonBlocking);
    cudaEvent_t evQ, evE;
    cudaEventCreateWithFlags(&evQ, cudaEventDisableTiming);
    cudaEventCreateWithFlags(&evE, cudaEventDisableTiming);

    const size_t half = (size_t)S_ * H_;   // 1024 rows

    // serial: converts then QKV projection (f16 output)
    conv_rows<<<(M_ * H_ / 4 + 255) / 256, 256>>>(hidden, Ah, M_ * H_ / 4);
    conv_transpose<<<dim3(NQKV_ / 32, H_ / 32), dim3(32, 8)>>>(Wqkv, Bq, H_, NQKV_);
    conv_transpose<<<dim3(H_ / 32, H_ / 32), dim3(32, 8)>>>(Wd, Bd, H_, H_);
    mma_gemm<false, true><<<dim3(M_ / 128, NQKV_ / 128), 128, GSM_TOTAL>>>(
        Ah, Bq, bqkv, nullptr, nullptr, QKV, NQKV_, H_);
    cudaEventRecord(evQ, 0);

    // s1: batch-1 attention then batch-1 dense
    cudaStreamWaitEvent(s1, evQ, 0);
    attn_mma<<<dim3(8, 32), 256, ATTN_SMEM, s1>>>(QKV, alibi, Ch, 1);
    mma_gemm<true, false><<<dim3(8, H_ / 128), 128, GSM_TOTAL, s1>>>(
        Ch + half, Bd, bd, residual + half, out + half, nullptr, H_, H_);
    cudaEventRecord(evE, s1);

    // main: batch-0 attention then batch-0 dense
    attn_mma<<<dim3(8, 32), 256, ATTN_SMEM>>>(QKV, alibi, Ch, 0);
    mma_gemm<true, false><<<dim3(8, H_ / 128), 128, GSM_TOTAL>>>(
        Ch, Bd, bd, residual, out, nullptr, H_, H_);

    // join
    cudaStreamWaitEvent(0, evE, 0);
}